// round 14
// baseline (speedup 1.0000x reference)
#include <cuda_runtime.h>
#include <cstdint>

#define BB 8
#define NN 1024
#define DD 64
#define HH 32

// Interleaved path assignment: 17 MUFU h's spread evenly among 32.
#define IS_MUFU(h) ((((h) + 1) * 17 >> 5) > ((h) * 17 >> 5))

#define ROWS_PU 16                 // rows per proj unit
#define N_PROJ_UNITS 1024          // 2*B*N/ROWS_PU
#define N_TILES 2048               // B * 16 * 16

// Scratch (allocation-free rule -> device globals).
__device__ float g_ca[BB * NN * HH];
__device__ float g_dv[BB * NN * HH];
__device__ unsigned int g_flag[N_PROJ_UNITS];   // per-unit ready flags
__device__ unsigned int g_obs;                  // consumers past their spin

using u64 = unsigned long long;

__device__ __forceinline__ u64 f2_add(u64 a, u64 b) {
    u64 r; asm("add.rn.f32x2 %0,%1,%2;" : "=l"(r) : "l"(a), "l"(b)); return r;
}
__device__ __forceinline__ u64 f2_mul(u64 a, u64 b) {
    u64 r; asm("mul.rn.f32x2 %0,%1,%2;" : "=l"(r) : "l"(a), "l"(b)); return r;
}
__device__ __forceinline__ u64 f2_fma(u64 a, u64 b, u64 c) {
    u64 r; asm("fma.rn.f32x2 %0,%1,%2,%3;" : "=l"(r) : "l"(a), "l"(b), "l"(c)); return r;
}
__device__ __forceinline__ u64 pack2(float lo, float hi) {
    u64 r; asm("mov.b64 %0,{%1,%2};" : "=l"(r) : "f"(lo), "f"(hi)); return r;
}
__device__ __forceinline__ void unpack2(u64 v, float& lo, float& hi) {
    asm("mov.b64 {%0,%1},%2;" : "=f"(lo), "=f"(hi) : "l"(v));
}
__device__ __forceinline__ float tanh_a(float x) {
    float r; asm("tanh.approx.f32 %0,%1;" : "=f"(r) : "f"(x)); return r;
}

#define ONE2 0x3F8000003F800000ULL

struct SmemP1 { float x[ROWS_PU][68]; float w[DD][HH]; };
struct SmemP2 { float u[64][36]; float v[HH][68]; u64 a2[HH]; };

// ---------------------------------------------------------------------------
// Fused single-launch dataflow kernel. Natural tile grid (2048 CTAs, 1 tile
// each). bids < 1024 first produce one 16-row projection unit and set its
// flag; every CTA spins only on the 8 unit-flags its tile needs.
// Producer mapping (b-interleaved so consumer deps are always lower bids):
//   p in [b*128, b*128+64)   -> cell rows b*1024 + (p&63)*16 ..     -> g_ca
//   p in [b*128+64, b*128+128) -> drug rows b*1024 + ((p&127)-64)*16 -> g_dv
// ---------------------------------------------------------------------------
__global__ __launch_bounds__(256, 5) void fused_kernel(
    const float* __restrict__ cell, const float* __restrict__ drug,
    const float* __restrict__ w_q, const float* __restrict__ w_k,
    const float* __restrict__ bias, const float* __restrict__ a_vec,
    float* __restrict__ out)
{
    __shared__ union { SmemP1 p1; SmemP2 p2; } sm;
    __shared__ int s_is_last;

    int tid = threadIdx.x;
    int bid = blockIdx.x;

    // ===================== Phase 1: one projection unit (bids < 1024) ==========
    if (bid < N_PROJ_UNITS) {
        int b  = bid >> 7;
        int r  = bid & 127;
        bool is_drug = r >= 64;
        int unit_row = is_drug ? (r - 64) : r;             // 0..63 within batch
        int row0 = b * NN + unit_row * ROWS_PU;            // global row in B*N
        const float* src = (is_drug ? drug : cell) + (size_t)row0 * DD;
        const float* W   = is_drug ? w_q : w_k;            // cell uses w_k

        // Stage x: 16 rows x 16 float4 = 256 float4, exactly 1 per thread.
        {
            int row = tid >> 4, d4 = tid & 15;
            float4 v = *reinterpret_cast<const float4*>(src + row * DD + d4 * 4);
            *reinterpret_cast<float4*>(&sm.p1.x[row][d4 * 4]) = v;
        }
        // Stage W: 512 float4, 2 per thread.
#pragma unroll
        for (int k = 0; k < 2; k++) {
            int idx = tid + k * 256;
            *reinterpret_cast<float4*>(reinterpret_cast<float*>(sm.p1.w) + idx * 4) =
                *reinterpret_cast<const float4*>(W + idx * 4);
        }
        __syncthreads();

        int hp  = tid & 15;      // h-pair: h = hp*2, hp*2+1
        int row = tid >> 4;      // 0..15

        float a0 = 0.f, a1 = 0.f;
#pragma unroll
        for (int d = 0; d < DD; d++) {
            float x = sm.p1.x[row][d];
            float2 w2 = *reinterpret_cast<float2*>(&sm.p1.w[d][hp * 2]);
            a0 = fmaf(x, w2.x, a0);
            a1 = fmaf(x, w2.y, a1);
        }

        int h0 = hp * 2;
        if (is_drug) {
            float2 b2 = *reinterpret_cast<const float2*>(bias + h0);
            a0 += b2.x; a1 += b2.y;
        }
        if (!IS_MUFU(h0))     a0 = tanh_a(a0);   // Newton lanes store tanh'd
        if (!IS_MUFU(h0 + 1)) a1 = tanh_a(a1);

        float* dst = (is_drug ? g_dv : g_ca) + (size_t)(row0 + row) * HH + h0;
        *reinterpret_cast<float2*>(dst) = make_float2(a0, a1);

        __threadfence();          // release: data visible before flag
        __syncthreads();          // all threads' stores fenced; smem WAR
        if (tid == 0) *(volatile unsigned int*)&g_flag[bid] = 1u;
    }

    // ===================== Tile indices + dataflow wait =====================
    int jx = bid & 15;
    int iy = (bid >> 4) & 15;
    int b  = bid >> 8;
    int i0 = iy * 64, j0 = jx * 64;

    if (tid < 8) {
        int k = tid & 3;
        int fidx = (tid < 4) ? (b * 128 + iy * 4 + k)
                             : (b * 128 + 64 + jx * 4 + k);
        while (*(volatile unsigned int*)&g_flag[fidx] == 0u)
            __nanosleep(32);
    }
    __syncthreads();              // all spins passed; no more flag reads

    if (tid == 0) {
        unsigned int o = atomicAdd(&g_obs, 1u);
        s_is_last = (o == (unsigned)(N_TILES - 1)) ? 1 : 0;
    }

    // ===================== Phase 2: one co-attention tile =====================
    const float* ca = g_ca + (b * NN + i0) * HH;
    const float* dv = g_dv + (b * NN + j0) * HH;

#pragma unroll
    for (int k = 0; k < 2; k++) {
        int idx = tid + k * 256;       // 0..511
        int row = idx >> 3, g = idx & 7;
        float4 uu = *reinterpret_cast<const float4*>(ca + row * HH + 4 * g);
        *reinterpret_cast<float4*>(&sm.p2.u[row][4 * g]) = uu;
        float4 vv = *reinterpret_cast<const float4*>(dv + row * HH + 4 * g);
        sm.p2.v[4 * g + 0][row] = vv.x;
        sm.p2.v[4 * g + 1][row] = vv.y;
        sm.p2.v[4 * g + 2][row] = vv.z;
        sm.p2.v[4 * g + 3][row] = vv.w;
    }
    if (tid < HH) {
        float av = a_vec[tid];
        if (!IS_MUFU(tid)) av = -av;   // folds r = -s*z sign on Newton path
        sm.p2.a2[tid] = pack2(av, av);
    }
    __syncthreads();

    // Reset protocol (2048th CTA past the spin; all flag reads are done).
    if (s_is_last) {
#pragma unroll
        for (int k = 0; k < 4; k++)
            g_flag[tid + k * 256] = 0u;
        if (tid == 0) { g_obs = 0u; }
        __threadfence();
    }

    int tx = tid & 15;        // j quad (4 consecutive cols -> float4 store)
    int ty = tid >> 4;        // i quad

    u64 acc[4][2];
#pragma unroll
    for (int r = 0; r < 4; r++) { acc[r][0] = 0ULL; acc[r][1] = 0ULL; }

#pragma unroll
    for (int g = 0; g < 16; g++) {                // h-groups of 2 (mixed paths)
        float2 u2r[4];
#pragma unroll
        for (int r = 0; r < 4; r++)
            u2r[r] = *reinterpret_cast<float2*>(&sm.p2.u[ty * 4 + r][2 * g]);

#pragma unroll
        for (int k = 0; k < 2; k++) {
            const int h = 2 * g + k;              // compile-time
            float4 vv = *reinterpret_cast<float4*>(&sm.p2.v[h][tx * 4]);
            u64 v2[2] = { pack2(vv.x, vv.y), pack2(vv.z, vv.w) };
            u64 a2 = sm.p2.a2[h];

#pragma unroll
            for (int r = 0; r < 4; r++) {
                float us = k ? u2r[r].y : u2r[r].x;
                u64 up = pack2(us, us);
#pragma unroll
                for (int cp = 0; cp < 2; cp++) {
                    u64 s2 = f2_add(up, v2[cp]);
                    if (IS_MUFU(h)) {
                        float lo, hi; unpack2(s2, lo, hi);
                        u64 t2 = pack2(tanh_a(lo), tanh_a(hi));
                        acc[r][cp] = f2_fma(a2, t2, acc[r][cp]);
                    } else {
                        u64 d2 = f2_fma(up, v2[cp], ONE2);          // d = 1+tu*tv
                        float dl, dh; unpack2(d2, dl, dh);
                        u64 z = pack2(                               // z0 ~ -1/d seed
                            __uint_as_float(0xFEF311C3u - __float_as_uint(dl)),
                            __uint_as_float(0xFEF311C3u - __float_as_uint(dh)));
                        u64 e = f2_fma(d2, z, ONE2);                 // e = 1 + d*z
                        u64 p = f2_fma(e, e, e);                     // e + e^2
                        z     = f2_fma(z, p, z);                     // -1/d, err e^3
                        u64 pp = f2_mul(s2, z);                      // -s/d
                        acc[r][cp] = f2_fma(a2, pp, acc[r][cp]);     // a2 pre-negated
                    }
                }
            }
        }
    }

#pragma unroll
    for (int r = 0; r < 4; r++) {
        float o0, o1, o2, o3;
        unpack2(acc[r][0], o0, o1);
        unpack2(acc[r][1], o2, o3);
        int i = i0 + ty * 4 + r;
        *reinterpret_cast<float4*>(out + ((size_t)b * NN + i) * NN + j0 + tx * 4) =
            make_float4(o0, o1, o2, o3);
    }
}

extern "C" void kernel_launch(void* const* d_in, const int* in_sizes, int n_in,
                              void* d_out, int out_size)
{
    const float* cell = (const float*)d_in[0];
    const float* drug = (const float*)d_in[1];
    const float* w_q  = (const float*)d_in[2];
    const float* w_k  = (const float*)d_in[3];
    const float* bias = (const float*)d_in[4];
    const float* a    = (const float*)d_in[5];
    float* out = (float*)d_out;

    fused_kernel<<<N_TILES, 256>>>(cell, drug, w_q, w_k, bias, a, out);
}